// round 2
// baseline (speedup 1.0000x reference)
#include <cuda_runtime.h>
#include <math.h>

#define BATCH 8
#define HEADS 8
#define LQ 512
#define LKK 512
#define DKK 64
#define NC 5
#define HD 512            // HEADS*DKK
#define KFLAT 262144      // HEADS*LKK*DKK
#define NCHUNK 64
#define CHSZ (KFLAT/NCHUNK)
#define BH (BATCH*HEADS)
#define FS_ELEMS ((size_t)BH*LQ*LKK)   // 16777216

// scratch (no allocations allowed)
__device__ float g_part[BATCH*NCHUNK*NC];
__device__ float g_means[NC*HD];
__device__ float g_dotp[(size_t)BH*LQ*40];   // P[row][cc*8+m], pre-scaled by 1/8

// ---------------------------------------------------------------------------
// Stage 1: partial sums for ck_proj = K.reshape(B,-1) @ W_proj
// ---------------------------------------------------------------------------
__global__ void ck_partial_kernel(const float* __restrict__ K,
                                  const float* __restrict__ Wp) {
    int b = blockIdx.y, ch = blockIdx.x, tid = threadIdx.x;
    float s[NC] = {0.f, 0.f, 0.f, 0.f, 0.f};
    const float* Kb = K + (size_t)b * KFLAT;
    int base = ch * CHSZ;
    for (int i = base + tid; i < base + CHSZ; i += 256) {
        float kv = Kb[i];
        const float* w = Wp + (size_t)i * NC;
        #pragma unroll
        for (int c = 0; c < NC; c++) s[c] = fmaf(kv, w[c], s[c]);
    }
    __shared__ float sm[NC][256];
    #pragma unroll
    for (int c = 0; c < NC; c++) sm[c][tid] = s[c];
    __syncthreads();
    for (int off = 128; off > 0; off >>= 1) {
        if (tid < off) {
            #pragma unroll
            for (int c = 0; c < NC; c++) sm[c][tid] += sm[c][tid + off];
        }
        __syncthreads();
    }
    if (tid < NC)
        g_part[((size_t)b * NCHUNK + ch) * NC + tid] = sm[tid][0];
}

// ---------------------------------------------------------------------------
// Stage 2: single block — softmaxes, loss, argmax, cluster means
// ---------------------------------------------------------------------------
__global__ void setup_kernel(const float* __restrict__ K,
                             const float* __restrict__ b_proj,
                             const float* __restrict__ W_q,
                             const float* __restrict__ b_q,
                             const float* __restrict__ W_k,
                             const float* __restrict__ b_k,
                             float* __restrict__ out) {
    int tid = threadIdx.x;
    __shared__ float s_ck[BATCH][NC], s_cq[BATCH][NC], s_ckk[BATCH][NC];
    __shared__ float s_mu[NC], s_sig[NC], s_ce[BATCH];
    __shared__ int   s_ind[BATCH];

    // reduce partials + bias
    if (tid < BATCH * NC) {
        int b = tid / NC, c = tid % NC;
        float s = b_proj[c];
        for (int ch = 0; ch < NCHUNK; ch++)
            s += g_part[((size_t)b * NCHUNK + ch) * NC + c];
        s_ck[b][c] = s;
    }
    __syncthreads();

    // per-batch: cluster_q / cluster_k softmaxes, argmax, entropy term
    if (tid < BATCH) {
        int b = tid;
        float vq[NC], vk[NC];
        #pragma unroll
        for (int c = 0; c < NC; c++) {
            float sq = b_q[c], sk = b_k[c];
            #pragma unroll
            for (int j = 0; j < NC; j++) {
                sq += s_ck[b][j] * W_q[j * NC + c];
                sk += s_ck[b][j] * W_k[j * NC + c];
            }
            vq[c] = sq; vk[c] = sk;
        }
        float mq = vq[0], mk = vk[0];
        #pragma unroll
        for (int c = 1; c < NC; c++) { mq = fmaxf(mq, vq[c]); mk = fmaxf(mk, vk[c]); }
        float zq = 0.f, zk = 0.f;
        #pragma unroll
        for (int c = 0; c < NC; c++) {
            vq[c] = expf(vq[c] - mq); zq += vq[c];
            vk[c] = expf(vk[c] - mk); zk += vk[c];
        }
        float best = -3.4e38f; int bi = 0;
        float pmax = -3.4e38f;
        #pragma unroll
        for (int c = 0; c < NC; c++) {
            float pq = vq[c] / zq;
            float pk = vk[c] / zk;
            s_cq[b][c]  = pq;
            s_ckk[b][c] = pk;
            if (pq > best) { best = pq; bi = c; }
            pmax = fmaxf(pmax, pq);
        }
        // ce_b = -sum q * log_softmax(q), input to log_softmax is q itself
        float z = 0.f;
        #pragma unroll
        for (int c = 0; c < NC; c++) z += expf(s_cq[b][c] - pmax);
        float lse = pmax + logf(z);
        float ce = 0.f;
        #pragma unroll
        for (int c = 0; c < NC; c++) ce -= s_cq[b][c] * (s_cq[b][c] - lse);
        s_ce[b]  = ce;
        s_ind[b] = bi;
    }
    __syncthreads();

    // per-cluster: mu = mean(cluster_q), sigma = softplus(std(cluster_k, ddof=1))
    if (tid < NC) {
        int c = tid;
        float mu = 0.f, mk = 0.f;
        #pragma unroll
        for (int b = 0; b < BATCH; b++) { mu += s_cq[b][c]; mk += s_ckk[b][c]; }
        mu *= 0.125f; mk *= 0.125f;
        float var = 0.f;
        #pragma unroll
        for (int b = 0; b < BATCH; b++) {
            float d = s_ckk[b][c] - mk;
            var += d * d;
        }
        var /= 7.0f;
        float sd = sqrtf(var);
        s_mu[c]  = mu;
        s_sig[c] = log1pf(expf(sd));
    }
    __syncthreads();

    // loss
    if (tid == 0) {
        float lp = 0.f;
        for (int b = 0; b < BATCH; b++)
            for (int c = 0; c < NC; c++) {
                float zz = (s_ckk[b][c] - s_mu[c]) / s_sig[c];
                lp += -0.5f * zz * zz - logf(s_sig[c]) - 0.91893853320467274f;
            }
        lp /= 40.0f;
        float ce = 0.f;
        for (int b = 0; b < BATCH; b++) ce += s_ce[b];
        ce *= 0.125f;
        out[FS_ELEMS] = -lp + ce;
    }
    __syncthreads();

    // row0[b][j] = K.reshape(b, l_k, hd)[:,0,:] = first HD floats of batch b
    // means[c][j] = (1/8) * sum_b [inds[b] != c+1] * K[b*KFLAT + j]
    for (int idx = tid; idx < NC * HD; idx += blockDim.x) {
        int c = idx / HD, j = idx % HD;
        float s = 0.f;
        #pragma unroll
        for (int b = 0; b < BATCH; b++)
            if (s_ind[b] != c + 1)
                s += K[(size_t)b * KFLAT + j];
        g_means[idx] = s * 0.125f;
    }
}

// ---------------------------------------------------------------------------
// Stage 3: P[row][cc*8+m] = scale * <Q[row,:], means[cc][m*64 : m*64+64]>
// The cm reshape in the reference maps cm2[b,h,c,k,d] = means[c'][(k&7)*64+d]
// with c' = (h*163840 + c*32768 + k*64) >> 18, so the epilogue only needs
// these 40 per-row dot products.
// ---------------------------------------------------------------------------
__global__ __launch_bounds__(256) void dotp_kernel(const float* __restrict__ Q) {
    __shared__ float sm[NC * HD];   // 2560 floats
    int tid = threadIdx.x;
    for (int i = tid; i < NC * HD; i += 256) sm[i] = g_means[i];
    __syncthreads();

    int row = blockIdx.x * 256 + tid;   // [0, BH*LQ)
    const float4* qr = (const float4*)(Q + (size_t)row * DKK);
    float4 qv[16];
    #pragma unroll
    for (int t = 0; t < 16; t++) qv[t] = qr[t];

    float* outp = g_dotp + (size_t)row * 40;
    #pragma unroll
    for (int cc = 0; cc < NC; cc++) {
        #pragma unroll
        for (int m = 0; m < 8; m++) {
            const float4* mp = (const float4*)(sm + cc * HD + m * 64);
            float s = 0.f;
            #pragma unroll
            for (int t = 0; t < 16; t++) {
                float4 mv = mp[t];
                s = fmaf(qv[t].x, mv.x, s);
                s = fmaf(qv[t].y, mv.y, s);
                s = fmaf(qv[t].z, mv.z, s);
                s = fmaf(qv[t].w, mv.w, s);
            }
            outp[cc * 8 + m] = s * 0.125f;
        }
    }
}

// ---------------------------------------------------------------------------
// Stage 4: batched GEMM, 128x64 tiles, 8x4 per thread, fused max epilogue
// ---------------------------------------------------------------------------
#define TQ 128
#define TK 64

__global__ __launch_bounds__(256) void gemm_kernel(const float* __restrict__ Q,
                                                   const float* __restrict__ K,
                                                   float* __restrict__ out) {
    __shared__ float Qs[DKK * TQ];   // [d][row]
    __shared__ float Ks[DKK * TK];   // [d][col]

    int qt = blockIdx.x, kt = blockIdx.y, bh = blockIdx.z;
    int tid = threadIdx.x;
    int tx = tid & 15, ty = tid >> 4;

    const float* Qb = Q + ((size_t)bh * LQ  + qt * TQ) * DKK;
    const float* Kb = K + ((size_t)bh * LKK + kt * TK) * DKK;

    // load Q tile (transpose into [d][row])
    for (int v = tid; v < TQ * 16; v += 256) {
        int row = v >> 4, dq = v & 15;
        float4 val = *(const float4*)(Qb + (size_t)row * DKK + dq * 4);
        Qs[(dq * 4 + 0) * TQ + row] = val.x;
        Qs[(dq * 4 + 1) * TQ + row] = val.y;
        Qs[(dq * 4 + 2) * TQ + row] = val.z;
        Qs[(dq * 4 + 3) * TQ + row] = val.w;
    }
    // load K tile (transpose into [d][col])
    for (int v = tid; v < TK * 16; v += 256) {
        int col = v >> 4, dq = v & 15;
        float4 val = *(const float4*)(Kb + (size_t)col * DKK + dq * 4);
        Ks[(dq * 4 + 0) * TK + col] = val.x;
        Ks[(dq * 4 + 1) * TK + col] = val.y;
        Ks[(dq * 4 + 2) * TK + col] = val.z;
        Ks[(dq * 4 + 3) * TK + col] = val.w;
    }
    __syncthreads();

    float acc[8][4];
    #pragma unroll
    for (int i = 0; i < 8; i++)
        #pragma unroll
        for (int j = 0; j < 4; j++) acc[i][j] = 0.f;

    #pragma unroll 8
    for (int kk = 0; kk < DKK; kk++) {
        float4 a0 = *(const float4*)&Qs[kk * TQ + ty * 8];
        float4 a1 = *(const float4*)&Qs[kk * TQ + ty * 8 + 4];
        float4 bv = *(const float4*)&Ks[kk * TK + tx * 4];
        float a[8] = {a0.x, a0.y, a0.z, a0.w, a1.x, a1.y, a1.z, a1.w};
        float b[4] = {bv.x, bv.y, bv.z, bv.w};
        #pragma unroll
        for (int i = 0; i < 8; i++)
            #pragma unroll
            for (int j = 0; j < 4; j++)
                acc[i][j] = fmaf(a[i], b[j], acc[i][j]);
    }

    // epilogue: fuse max with the cm-derived scores
    int h = bh & 7;
    int row0 = qt * TQ + ty * 8;
    const float* Pbase = g_dotp + ((size_t)bh * LQ + row0) * 40;

    int offA[4], offB[4];
    #pragma unroll
    for (int j = 0; j < 4; j++) {
        int kg = kt * TK + tx * 4 + j;
        int m = kg & 7;
        int u = h * 163840 + kg * 64;
        offA[j] = ((u) >> 18) * 8 + m;
        offB[j] = ((u + 131072) >> 18) * 8 + m;
    }

    #pragma unroll
    for (int i = 0; i < 8; i++) {
        const float* Pr = Pbase + i * 40;
        float4 o;
        float qc0 = fmaxf(Pr[offA[0]], Pr[offB[0]]);
        float qc1 = fmaxf(Pr[offA[1]], Pr[offB[1]]);
        float qc2 = fmaxf(Pr[offA[2]], Pr[offB[2]]);
        float qc3 = fmaxf(Pr[offA[3]], Pr[offB[3]]);
        o.x = fmaxf(acc[i][0] * 0.125f, qc0);
        o.y = fmaxf(acc[i][1] * 0.125f, qc1);
        o.z = fmaxf(acc[i][2] * 0.125f, qc2);
        o.w = fmaxf(acc[i][3] * 0.125f, qc3);
        *(float4*)(out + ((size_t)bh * LQ + row0 + i) * LKK + kt * TK + tx * 4) = o;
    }
}

// ---------------------------------------------------------------------------
extern "C" void kernel_launch(void* const* d_in, const int* in_sizes, int n_in,
                              void* d_out, int out_size) {
    const float* Q  = (const float*)d_in[0];
    const float* K  = (const float*)d_in[1];
    const float* Wp = (const float*)d_in[2];
    const float* bp = (const float*)d_in[3];
    const float* Wq = (const float*)d_in[4];
    const float* bq = (const float*)d_in[5];
    const float* Wk = (const float*)d_in[6];
    const float* bk = (const float*)d_in[7];
    float* out = (float*)d_out;

    ck_partial_kernel<<<dim3(NCHUNK, BATCH), 256>>>(K, Wp);
    setup_kernel<<<1, 256>>>(K, bp, Wq, bq, Wk, bk, out);
    dotp_kernel<<<(BH * LQ) / 256, 256>>>(Q);
    gemm_kernel<<<dim3(LQ / TQ, LKK / TK, BH), 256>>>(Q, K, out);
}

// round 4
// speedup vs baseline: 2.1149x; 2.1149x over previous
#include <cuda_runtime.h>
#include <cuda_bf16.h>
#include <math.h>
#include <stdint.h>

#define BATCH 8
#define HEADS 8
#define LQ 512
#define LKK 512
#define DKK 64
#define NC 5
#define HD 512            // HEADS*DKK
#define KFLAT 262144      // HEADS*LKK*DKK
#define NCHUNK 64
#define CHSZ (KFLAT/NCHUNK)
#define BH (BATCH*HEADS)
#define FS_ELEMS ((size_t)BH*LQ*LKK)   // 16777216

// scratch (no allocations allowed)
__device__ float g_part[BATCH*NCHUNK*NC];
__device__ float g_means[NC*HD];
__device__ float g_qcm[(size_t)BH*LQ*8];   // qcm[row][m], pre-scaled by 1/8

__device__ __forceinline__ uint32_t smem_u32(const void* p) {
    uint32_t a;
    asm("{ .reg .u64 t; cvta.to.shared.u64 t, %1; cvt.u32.u64 %0, t; }"
        : "=r"(a) : "l"(p));
    return a;
}

// ---------------------------------------------------------------------------
// Stage 1: partial sums for ck_proj = K.reshape(B,-1) @ W_proj
// ---------------------------------------------------------------------------
__global__ void ck_partial_kernel(const float* __restrict__ K,
                                  const float* __restrict__ Wp) {
    int b = blockIdx.y, ch = blockIdx.x, tid = threadIdx.x;
    float s[NC] = {0.f, 0.f, 0.f, 0.f, 0.f};
    const float* Kb = K + (size_t)b * KFLAT;
    int base = ch * CHSZ;
    for (int i = base + tid; i < base + CHSZ; i += 256) {
        float kv = Kb[i];
        const float* w = Wp + (size_t)i * NC;
        #pragma unroll
        for (int c = 0; c < NC; c++) s[c] = fmaf(kv, w[c], s[c]);
    }
    __shared__ float sm[NC][256];
    #pragma unroll
    for (int c = 0; c < NC; c++) sm[c][tid] = s[c];
    __syncthreads();
    for (int off = 128; off > 0; off >>= 1) {
        if (tid < off) {
            #pragma unroll
            for (int c = 0; c < NC; c++) sm[c][tid] += sm[c][tid + off];
        }
        __syncthreads();
    }
    if (tid < NC)
        g_part[((size_t)b * NCHUNK + ch) * NC + tid] = sm[tid][0];
}

// ---------------------------------------------------------------------------
// Stage 2: single block — softmaxes, loss, argmax, cluster means
// ---------------------------------------------------------------------------
__global__ void setup_kernel(const float* __restrict__ K,
                             const float* __restrict__ b_proj,
                             const float* __restrict__ W_q,
                             const float* __restrict__ b_q,
                             const float* __restrict__ W_k,
                             const float* __restrict__ b_k,
                             float* __restrict__ out) {
    int tid = threadIdx.x;
    __shared__ float s_ck[BATCH][NC], s_cq[BATCH][NC], s_ckk[BATCH][NC];
    __shared__ float s_mu[NC], s_sig[NC], s_ce[BATCH];
    __shared__ int   s_ind[BATCH];

    if (tid < BATCH * NC) {
        int b = tid / NC, c = tid % NC;
        float s = b_proj[c];
        for (int ch = 0; ch < NCHUNK; ch++)
            s += g_part[((size_t)b * NCHUNK + ch) * NC + c];
        s_ck[b][c] = s;
    }
    __syncthreads();

    if (tid < BATCH) {
        int b = tid;
        float vq[NC], vk[NC];
        #pragma unroll
        for (int c = 0; c < NC; c++) {
            float sq = b_q[c], sk = b_k[c];
            #pragma unroll
            for (int j = 0; j < NC; j++) {
                sq += s_ck[b][j] * W_q[j * NC + c];
                sk += s_ck[b][j] * W_k[j * NC + c];
            }
            vq[c] = sq; vk[c] = sk;
        }
        float mq = vq[0], mk = vk[0];
        #pragma unroll
        for (int c = 1; c < NC; c++) { mq = fmaxf(mq, vq[c]); mk = fmaxf(mk, vk[c]); }
        float zq = 0.f, zk = 0.f;
        #pragma unroll
        for (int c = 0; c < NC; c++) {
            vq[c] = expf(vq[c] - mq); zq += vq[c];
            vk[c] = expf(vk[c] - mk); zk += vk[c];
        }
        float best = -3.4e38f; int bi = 0;
        float pmax = -3.4e38f;
        #pragma unroll
        for (int c = 0; c < NC; c++) {
            float pq = vq[c] / zq;
            float pk = vk[c] / zk;
            s_cq[b][c]  = pq;
            s_ckk[b][c] = pk;
            if (pq > best) { best = pq; bi = c; }
            pmax = fmaxf(pmax, pq);
        }
        float z = 0.f;
        #pragma unroll
        for (int c = 0; c < NC; c++) z += expf(s_cq[b][c] - pmax);
        float lse = pmax + logf(z);
        float ce = 0.f;
        #pragma unroll
        for (int c = 0; c < NC; c++) ce -= s_cq[b][c] * (s_cq[b][c] - lse);
        s_ce[b]  = ce;
        s_ind[b] = bi;
    }
    __syncthreads();

    if (tid < NC) {
        int c = tid;
        float mu = 0.f, mk = 0.f;
        #pragma unroll
        for (int b = 0; b < BATCH; b++) { mu += s_cq[b][c]; mk += s_ckk[b][c]; }
        mu *= 0.125f; mk *= 0.125f;
        float var = 0.f;
        #pragma unroll
        for (int b = 0; b < BATCH; b++) {
            float d = s_ckk[b][c] - mk;
            var += d * d;
        }
        var /= 7.0f;
        float sd = sqrtf(var);
        s_mu[c]  = mu;
        s_sig[c] = log1pf(expf(sd));
    }
    __syncthreads();

    if (tid == 0) {
        float lp = 0.f;
        for (int b = 0; b < BATCH; b++)
            for (int c = 0; c < NC; c++) {
                float zz = (s_ckk[b][c] - s_mu[c]) / s_sig[c];
                lp += -0.5f * zz * zz - logf(s_sig[c]) - 0.91893853320467274f;
            }
        lp /= 40.0f;
        float ce = 0.f;
        for (int b = 0; b < BATCH; b++) ce += s_ce[b];
        ce *= 0.125f;
        out[FS_ELEMS] = -lp + ce;
    }
    __syncthreads();

    // means[c][j] = (1/8) * sum_b [inds[b] != c+1] * K[b*KFLAT + j]
    for (int idx = tid; idx < NC * HD; idx += blockDim.x) {
        int c = idx / HD, j = idx % HD;
        float s = 0.f;
        #pragma unroll
        for (int b = 0; b < BATCH; b++)
            if (s_ind[b] != c + 1)
                s += K[(size_t)b * KFLAT + j];
        g_means[idx] = s * 0.125f;
    }
}

// ---------------------------------------------------------------------------
// Stage 3: qcm[row][m] = scale * max(dot(Q,means[ccA][m*64:]), dot(Q,means[ccB][m*64:]))
// ---------------------------------------------------------------------------
__global__ __launch_bounds__(256) void dotp_kernel(const float* __restrict__ Q) {
    __shared__ float sm[NC * HD];
    int tid = threadIdx.x;
    for (int i = tid; i < NC * HD; i += 256) sm[i] = g_means[i];
    __syncthreads();

    int row = blockIdx.x * 256 + tid;   // [0, BH*LQ)
    int bh = row >> 9;
    int h  = bh & 7;
    int ccA = (h * 163840) >> 18;
    int ccB = (h * 163840 + 131072) >> 18;

    const float4* qr = (const float4*)(Q + (size_t)row * DKK);
    float4 qv[16];
    #pragma unroll
    for (int t = 0; t < 16; t++) qv[t] = qr[t];

    float* outp = g_qcm + (size_t)row * 8;
    #pragma unroll
    for (int m = 0; m < 8; m++) {
        const float4* ma = (const float4*)(sm + ccA * HD + m * 64);
        const float4* mb = (const float4*)(sm + ccB * HD + m * 64);
        float sa = 0.f, sb = 0.f;
        #pragma unroll
        for (int t = 0; t < 16; t++) {
            float4 av = ma[t], bv = mb[t];
            sa = fmaf(qv[t].x, av.x, sa); sa = fmaf(qv[t].y, av.y, sa);
            sa = fmaf(qv[t].z, av.z, sa); sa = fmaf(qv[t].w, av.w, sa);
            sb = fmaf(qv[t].x, bv.x, sb); sb = fmaf(qv[t].y, bv.y, sb);
            sb = fmaf(qv[t].z, bv.z, sb); sb = fmaf(qv[t].w, bv.w, sb);
        }
        outp[m] = fmaxf(sa, sb) * 0.125f;
    }
}

// ---------------------------------------------------------------------------
// Stage 4: mma.sync bf16-split GEMM (3 passes: hh, hl, lh).
// CTA 128x128, K=64 resident; 8 warps, warp tile 64x32.
// ---------------------------------------------------------------------------
#define STRIDE 72                       // bf16 elems per smem row (pad 64->72)
#define AH_OFF 0
#define AL_OFF 18432
#define BHI_OFF 36864
#define BLO_OFF 55296
#define SMEM_BYTES 73728

#define LDSM_X4(r0, r1, r2, r3, addr) \
    asm volatile("ldmatrix.sync.aligned.m8n8.x4.shared.b16 {%0,%1,%2,%3}, [%4];" \
                 : "=r"(r0), "=r"(r1), "=r"(r2), "=r"(r3) : "r"(addr))

#define MMA_BF16(c, a, b) \
    asm volatile("mma.sync.aligned.m16n8k16.row.col.f32.bf16.bf16.f32 " \
                 "{%0,%1,%2,%3}, {%4,%5,%6,%7}, {%8,%9}, {%0,%1,%2,%3};" \
                 : "+f"((c)[0]), "+f"((c)[1]), "+f"((c)[2]), "+f"((c)[3]) \
                 : "r"((a)[0]), "r"((a)[1]), "r"((a)[2]), "r"((a)[3]), \
                   "r"((b)[0]), "r"((b)[1]))

__device__ __forceinline__ uint32_t pack_bf2(__nv_bfloat16 a, __nv_bfloat16 b) {
    __nv_bfloat162 t(a, b);
    return *reinterpret_cast<uint32_t*>(&t);
}
__device__ __forceinline__ void split4(float4 v, uint2& hi, uint2& lo) {
    float f[4] = {v.x, v.y, v.z, v.w};
    __nv_bfloat16 h[4], l[4];
    #pragma unroll
    for (int i = 0; i < 4; i++) {
        h[i] = __float2bfloat16_rn(f[i]);
        l[i] = __float2bfloat16_rn(f[i] - __bfloat162float(h[i]));
    }
    hi.x = pack_bf2(h[0], h[1]); hi.y = pack_bf2(h[2], h[3]);
    lo.x = pack_bf2(l[0], l[1]); lo.y = pack_bf2(l[2], l[3]);
}

__global__ __launch_bounds__(256, 2) void hmma_kernel(const float* __restrict__ Q,
                                                      const float* __restrict__ K,
                                                      float* __restrict__ out) {
    extern __shared__ char smem[];
    uint32_t sbase = smem_u32(smem);
    int tid = threadIdx.x;
    int wid = tid >> 5, lane = tid & 31;
    int qt = blockIdx.x, kt = blockIdx.y, bh = blockIdx.z;

    // ---- load + convert Q tile (128x64) and K tile (128x64) ----
    const float4* Qb = (const float4*)(Q + ((size_t)bh * LQ + qt * 128) * DKK);
    const float4* Kb = (const float4*)(K + ((size_t)bh * LKK + kt * 128) * DKK);
    for (int v = tid; v < 128 * 16; v += 256) {
        int row = v >> 4, c4 = v & 15;
        uint32_t boff = (row * STRIDE + c4 * 4) * 2;
        uint2 hi, lo;
        split4(Qb[v], hi, lo);
        *(uint2*)(smem + AH_OFF + boff) = hi;
        *(uint2*)(smem + AL_OFF + boff) = lo;
        split4(Kb[v], hi, lo);
        *(uint2*)(smem + BHI_OFF + boff) = hi;
        *(uint2*)(smem + BLO_OFF + boff) = lo;
    }
    __syncthreads();

    // ---- warp tiling: 2 (m) x 4 (n) warps, warp tile 64x32 ----
    int wm = (wid & 1) * 64;
    int wn = (wid >> 1) * 32;

    // ldmatrix lane->element offsets
    int arow = lane & 15;
    int akd  = (lane >> 4) << 3;
    int brow = (lane & 7) | ((lane >> 4) << 3);
    int bkd  = lane & 8;

    float acc[4][4][4];
    #pragma unroll
    for (int mt = 0; mt < 4; mt++)
        #pragma unroll
        for (int nt = 0; nt < 4; nt++)
            #pragma unroll
            for (int r = 0; r < 4; r++) acc[mt][nt][r] = 0.f;

    uint32_t a_base[2] = {sbase + AH_OFF, sbase + AL_OFF};
    uint32_t b_base[2] = {sbase + BHI_OFF, sbase + BLO_OFF};
    int pa[3] = {0, 0, 1};   // hh, hl, lh
    int pb[3] = {0, 1, 0};

    #pragma unroll
    for (int p = 0; p < 3; p++) {
        uint32_t Ab = a_base[pa[p]];
        uint32_t Bb = b_base[pb[p]];
        #pragma unroll
        for (int ks = 0; ks < 4; ks++) {
            int k0 = ks * 16;
            uint32_t af[4][4];
            #pragma unroll
            for (int mt = 0; mt < 4; mt++) {
                uint32_t addr = Ab + ((wm + mt * 16 + arow) * STRIDE + k0 + akd) * 2;
                LDSM_X4(af[mt][0], af[mt][1], af[mt][2], af[mt][3], addr);
            }
            uint32_t bf[4][2];
            #pragma unroll
            for (int n2 = 0; n2 < 2; n2++) {
                uint32_t addr = Bb + ((wn + n2 * 16 + brow) * STRIDE + k0 + bkd) * 2;
                LDSM_X4(bf[n2 * 2][0], bf[n2 * 2][1],
                        bf[n2 * 2 + 1][0], bf[n2 * 2 + 1][1], addr);
            }
            #pragma unroll
            for (int mt = 0; mt < 4; mt++)
                #pragma unroll
                for (int nt = 0; nt < 4; nt++)
                    MMA_BF16(acc[mt][nt], af[mt], bf[nt]);
        }
    }

    // ---- epilogue: scale, max with qcm, store ----
    int g = lane >> 2, q4 = lane & 3;
    #pragma unroll
    for (int mt = 0; mt < 4; mt++) {
        int r0 = qt * 128 + wm + mt * 16 + g;
        float2 qv0 = *(const float2*)(g_qcm + ((size_t)bh * LQ + r0) * 8 + q4 * 2);
        float2 qv1 = *(const float2*)(g_qcm + ((size_t)bh * LQ + r0 + 8) * 8 + q4 * 2);
        float* row0 = out + ((size_t)bh * LQ + r0) * LKK + kt * 128;
        float* row1 = row0 + 8 * LKK;
        #pragma unroll
        for (int nt = 0; nt < 4; nt++) {
            int c = wn + nt * 8 + q4 * 2;
            float2 o0, o1;
            o0.x = fmaxf(acc[mt][nt][0] * 0.125f, qv0.x);
            o0.y = fmaxf(acc[mt][nt][1] * 0.125f, qv0.y);
            o1.x = fmaxf(acc[mt][nt][2] * 0.125f, qv1.x);
            o1.y = fmaxf(acc[mt][nt][3] * 0.125f, qv1.y);
            *(float2*)(row0 + c) = o0;
            *(float2*)(row1 + c) = o1;
        }
    }
}

// ---------------------------------------------------------------------------
extern "C" void kernel_launch(void* const* d_in, const int* in_sizes, int n_in,
                              void* d_out, int out_size) {
    const float* Q  = (const float*)d_in[0];
    const float* K  = (const float*)d_in[1];
    const float* Wp = (const float*)d_in[2];
    const float* bp = (const float*)d_in[3];
    const float* Wq = (const float*)d_in[4];
    const float* bq = (const float*)d_in[5];
    const float* Wk = (const float*)d_in[6];
    const float* bk = (const float*)d_in[7];
    float* out = (float*)d_out;

    cudaFuncSetAttribute(hmma_kernel,
                         cudaFuncAttributeMaxDynamicSharedMemorySize, SMEM_BYTES);

    ck_partial_kernel<<<dim3(NCHUNK, BATCH), 256>>>(K, Wp);
    setup_kernel<<<1, 256>>>(K, bp, Wq, bq, Wk, bk, out);
    dotp_kernel<<<(BH * LQ) / 256, 256>>>(Q);
    hmma_kernel<<<dim3(LQ / 128, LKK / 128, BH), 256, SMEM_BYTES>>>(Q, K, out);
}